// round 15
// baseline (speedup 1.0000x reference)
#include <cuda_runtime.h>

#define BB 2
#define NN 49104
#define CC 20
#define NPAD 49152
#define MAXDET 300
#define NEGV (-1e9f)
#define NEG_HALF (-5e8f)
#define NTHR 1024
#define ELEMS (NPAD / NTHR)   // 48
#define FLATN (CC * MAXDET)   // 6000
#define TARGETC 1792
#define CAND_CAP 4096
#define GSZ 256
#define GW (GSZ / 32)         // 8 mask words
#define TAU 0.5536f           // round-0 pool cutoff: m ~ 3800 +- 59 (5 sigma < 4096)

// ---------------- device scratch ----------------
__device__ float4 g_boxes[BB * NN];
__device__ float  g_nms_sc[BB * FLATN];
__device__ int    g_nms_idx[BB * FLATN];

// ---------------- warp helpers ----------------
__device__ __forceinline__ void hist_add(int* hist, int bin, bool flag) {
    unsigned act = __ballot_sync(0xffffffffu, flag);
    if (flag) {
        unsigned peers = __match_any_sync(act, bin);
        int leader = __ffs(peers) - 1;
        if ((int)(threadIdx.x & 31) == leader) atomicAdd(&hist[bin], __popc(peers));
    }
}

__device__ __forceinline__ int warp_agg_inc(int* ctr, bool flag) {
    unsigned act = __ballot_sync(0xffffffffu, flag);
    if (flag) {
        int lane = threadIdx.x & 31;
        int leader = __ffs(act) - 1;
        int base = 0;
        if (lane == leader) base = atomicAdd(ctr, __popc(act));
        base = __shfl_sync(act, base, leader);
        return base + __popc(act & ((1u << lane) - 1u));
    }
    return -1;
}

// ---------------- decode + clip (exact) ----------------
__global__ void prep_kernel(const float* __restrict__ anchors,
                            const float* __restrict__ deltas) {
    int i = blockIdx.x * blockDim.x + threadIdx.x;
    if (i >= BB * NN) return;
    float4 a = ((const float4*)anchors)[i];
    float4 d = ((const float4*)deltas)[i];
    float w = __fsub_rn(a.z, a.x);
    float h = __fsub_rn(a.w, a.y);
    float x1 = __fadd_rn(a.x, __fmul_rn(__fmul_rn(d.x, 0.2f), w));
    float y1 = __fadd_rn(a.y, __fmul_rn(__fmul_rn(d.y, 0.2f), h));
    float x2 = __fadd_rn(a.z, __fmul_rn(__fmul_rn(d.z, 0.2f), w));
    float y2 = __fadd_rn(a.w, __fmul_rn(__fmul_rn(d.w, 0.2f), h));
    x1 = fminf(fmaxf(x1, 0.0f), 511.0f);
    y1 = fminf(fmaxf(y1, 0.0f), 511.0f);
    x2 = fminf(fmaxf(x2, 0.0f), 511.0f);
    y2 = fminf(fmaxf(y2, 0.0f), 511.0f);
    g_boxes[i] = make_float4(x1, y1, x2, y2);
}

// exact IoU > 0.5 (bit-identical to reference; symmetric)
__device__ __forceinline__ bool iou_gt_half(float4 a, float4 b) {
    float xx1 = fmaxf(a.x, b.x);
    float yy1 = fmaxf(a.y, b.y);
    float xx2 = fminf(a.z, b.z);
    float yy2 = fminf(a.w, b.w);
    float iw = fmaxf(__fsub_rn(xx2, xx1), 0.0f);
    float ih = fmaxf(__fsub_rn(yy2, yy1), 0.0f);
    float inter = __fmul_rn(iw, ih);
    float aa = __fmul_rn(__fsub_rn(a.z, a.x), __fsub_rn(a.w, a.y));
    float ab = __fmul_rn(__fsub_rn(b.z, b.x), __fsub_rn(b.w, b.y));
    float den = __fadd_rn(__fsub_rn(__fadd_rn(aa, ab), inter), 1e-8f);
    return __fdiv_rn(inter, den) > 0.5f;
}

// ---------------- per (batch, class) sorted-order greedy NMS ----------------
__global__ __launch_bounds__(NTHR, 1) void nms_pair_kernel(const float* __restrict__ cls) {
    extern __shared__ unsigned long long cand[];   // CAND_CAP u64 = 32KB dynamic
    __shared__ int      s_hist[256];
    __shared__ int      s_total;
    __shared__ int      s_target;
    __shared__ unsigned s_prefix;
    __shared__ int      s_cnt;
    __shared__ unsigned long long s_bound;
    __shared__ float4   s_acc[MAXDET];
    __shared__ int      s_accN;
    __shared__ float4   s_gbox[GSZ];
    __shared__ uint4    s_mask4[GSZ * 2];          // 256 rows x 8 words (16B aligned)
    __shared__ unsigned s_dead[GW];

    unsigned* s_mask = (unsigned*)s_mask4;
    int pair = blockIdx.x;
    int b = pair / CC;
    int c = pair % CC;
    int t = threadIdx.x;
    const float* __restrict__ sp = cls + (size_t)b * NN * CC + c;   // score(n) = sp[n*CC]
    const float4* __restrict__ bx = g_boxes + b * NN;

    if (t < MAXDET) {
        g_nms_sc[pair * MAXDET + t] = NEGV;
        g_nms_idx[pair * MAXDET + t] = 0;
    }
    if (t == 0) { s_accN = 0; s_bound = ~0ull; }

    for (int round = 0; ; round++) {
        __syncthreads();
        if (s_accN >= MAXDET) break;
        unsigned long long bound = s_bound;
        int m;

        if (round == 0) {
            // ---- fast path: fixed-cutoff compaction, no histogram ----
            if (t == 0) s_cnt = 0;
            __syncthreads();
            unsigned tau_u = __float_as_uint(TAU);
#pragma unroll 8
            for (int k = 0; k < ELEMS; k++) {
                int n = t + k * NTHR;
                float v = (n < NN) ? __ldg(sp + (size_t)n * CC) : -1.0f;
                bool f = (v > TAU);
                unsigned long long key = 0;
                if (f) {
                    unsigned u = __float_as_uint(v);
                    key = ((unsigned long long)u << 32) | (unsigned)(0xFFFFFFFFu - (unsigned)n);
                }
                int pos = warp_agg_inc(&s_cnt, f);
                if (f && pos < CAND_CAP) cand[pos] = key;
            }
            __syncthreads();
            if (s_cnt > CAND_CAP || s_cnt == 0) continue;   // exact fallback handles it
            m = s_cnt;
            if (t == 0)   // everything with score > TAU is processed this round
                s_bound = ((unsigned long long)(tau_u + 1)) << 32;
        } else {
            // ---- exact 4-level byte-radix select among remaining ----
            if (t == 0) { s_prefix = 0u; s_total = 0; s_target = 0; }
            __syncthreads();
            unsigned prefix = 0u;
            for (int lvl = 0; lvl < 4; lvl++) {
                int shift = 24 - lvl * 8;
                if (t < 256) s_hist[t] = 0;
                __syncthreads();
                unsigned himask = (lvl == 0) ? 0u : (0xFFFFFFFFu << (shift + 8));
                for (int k = 0; k < ELEMS; k++) {
                    int n = t + k * NTHR;
                    float v = (n < NN) ? __ldg(sp + (size_t)n * CC) : -1.0f;
                    bool f = false;
                    int bin = 0;
                    if (v > 0.05f) {
                        unsigned u = __float_as_uint(v);
                        if ((u & himask) == (prefix & himask)) {
                            unsigned long long key =
                                ((unsigned long long)u << 32) | (unsigned)(0xFFFFFFFFu - (unsigned)n);
                            if (key < bound) { f = true; bin = (u >> shift) & 255; }
                        }
                    }
                    hist_add(s_hist, bin, f);
                }
                __syncthreads();
                if (t == 0) {
                    if (lvl == 0) {
                        int tot = 0;
                        for (int i = 0; i < 256; i++) tot += s_hist[i];
                        s_total = tot;
                        s_target = tot < TARGETC ? tot : TARGETC;
                    }
                    if (s_total > 0) {
                        int cum = 0, bin = 0;
                        for (int i = 255; i >= 0; i--) {
                            int h = s_hist[i];
                            if (cum + h >= s_target) { bin = i; break; }
                            cum += h;
                        }
                        s_target -= cum;
                        s_prefix |= (unsigned)bin << shift;
                    }
                }
                __syncthreads();
                prefix = s_prefix;
                if (s_total == 0) break;
            }
            if (s_total == 0) break;   // pool exhausted -> remaining slots stay NEG
            unsigned s_star = prefix;

            if (t == 0) s_cnt = 0;
            __syncthreads();
#pragma unroll 8
            for (int k = 0; k < ELEMS; k++) {
                int n = t + k * NTHR;
                float v = (n < NN) ? __ldg(sp + (size_t)n * CC) : -1.0f;
                bool f = false;
                unsigned long long key = 0;
                if (v > 0.05f) {
                    unsigned u = __float_as_uint(v);
                    if (u >= s_star) {
                        key = ((unsigned long long)u << 32) | (unsigned)(0xFFFFFFFFu - (unsigned)n);
                        if (key < bound) f = true;
                    }
                }
                int pos = warp_agg_inc(&s_cnt, f);
                if (f && pos < CAND_CAP) cand[pos] = key;
            }
            __syncthreads();
            m = s_cnt < CAND_CAP ? s_cnt : CAND_CAP;
        }

        // ---- pad + bitonic sort descending (warp-sync small substeps) ----
        int sortn = 512;
        while (sortn < m) sortn <<= 1;
        for (int i = m + t; i < sortn; i += NTHR) cand[i] = 0ull;
        __syncthreads();
        for (int k2 = 2; k2 <= sortn; k2 <<= 1) {
            for (int j = k2 >> 1; j > 0; j >>= 1) {
                for (int i = t; i < sortn; i += NTHR) {
                    int l = i ^ j;
                    if (l > i) {
                        unsigned long long a = cand[i];
                        unsigned long long bb = cand[l];
                        bool up = ((i & k2) == 0);
                        bool sw = up ? (a < bb) : (a > bb);
                        if (sw) { cand[i] = bb; cand[l] = a; }
                    }
                }
                int nj = (j > 1) ? (j >> 1) : k2;
                if (j >= 32 || nj >= 32) __syncthreads();
                else __syncwarp();
            }
        }
        if (round > 0) {
            if (t == 0) s_bound = cand[m - 1];
            __syncthreads();
        }

        // ---- walk sorted candidates in groups of GSZ ----
        for (int g0 = 0; g0 < m && s_accN < MAXDET; g0 += GSZ) {
            int gsz = min(GSZ, m - g0);
            for (int i = t; i < GSZ * 2; i += NTHR) s_mask4[i] = make_uint4(0, 0, 0, 0);
            if (t < GW) s_dead[t] = 0u;
            if (t < gsz) {
                unsigned long long key = cand[g0 + t];
                unsigned n = 0xFFFFFFFFu - (unsigned)(key & 0xFFFFFFFFull);
                s_gbox[t] = __ldg(&bx[n]);
            }
            __syncthreads();

            int j = t & (GSZ - 1);
            int seg = t >> 8;     // 4 work segments per candidate
            if (j < gsz) {
                float4 cb = s_gbox[j];
                bool dead = false;
                int accN = s_accN;
                for (int i = seg; i < accN; i += 4)
                    if (iou_gt_half(s_acc[i], cb)) { dead = true; break; }
                if (dead) atomicOr(&s_dead[j >> 5], 1u << (j & 31));
                for (int i = seg; i < j; i += 4)
                    if (iou_gt_half(s_gbox[i], cb))
                        atomicOr(&s_mask[i * GW + (j >> 5)], 1u << (j & 31));
            }
            __syncthreads();

            // serial in-order resolution by t0: register-resident alive mask
            if (t == 0) {
                unsigned aw[GW];
#pragma unroll
                for (int w = 0; w < GW; w++) {
                    int rem = gsz - w * 32;
                    unsigned valid = (rem >= 32) ? 0xFFFFFFFFu
                                   : (rem <= 0 ? 0u : ((1u << rem) - 1u));
                    aw[w] = ~s_dead[w] & valid;
                }
                int acc = s_accN;
                while (acc < MAXDET) {
                    int jj = -1;
#pragma unroll
                    for (int w = GW - 1; w >= 0; w--)
                        if (aw[w]) jj = w * 32 + __ffs(aw[w]) - 1;
                    if (jj < 0) break;
                    uint4 m0 = s_mask4[jj * 2];
                    uint4 m1 = s_mask4[jj * 2 + 1];
                    aw[jj >> 5] &= ~(1u << (jj & 31));
                    aw[0] &= ~m0.x; aw[1] &= ~m0.y; aw[2] &= ~m0.z; aw[3] &= ~m0.w;
                    aw[4] &= ~m1.x; aw[5] &= ~m1.y; aw[6] &= ~m1.z; aw[7] &= ~m1.w;
                    unsigned long long key = cand[g0 + jj];
                    unsigned n = 0xFFFFFFFFu - (unsigned)(key & 0xFFFFFFFFull);
                    g_nms_sc[pair * MAXDET + acc] = __uint_as_float((unsigned)(key >> 32));
                    g_nms_idx[pair * MAXDET + acc] = (int)n;
                    s_acc[acc] = s_gbox[jj];
                    acc++;
                }
                s_accN = acc;
            }
            __syncthreads();
        }
    }
}

// ------- merge: exact 6-level u64 radix select (parallel bin scan) + tiny sort -------
__global__ __launch_bounds__(NTHR, 1) void merge_kernel(float* __restrict__ out) {
    __shared__ int      s_hist[256];
    __shared__ int      s_wsum[8];
    __shared__ unsigned long long s_prefix;
    __shared__ int      s_target;
    __shared__ int      s_newbin;
    __shared__ int      s_newtarget;
    __shared__ int      s_cnt;
    __shared__ unsigned long long ck[512];
    int b = blockIdx.x;
    int t = threadIdx.x;

    unsigned long long key[6];
    bool kv[6];
#pragma unroll
    for (int k = 0; k < 6; k++) {
        int i = t + k * NTHR;
        kv[k] = (i < FLATN);
        key[k] = 0ull;
        if (kv[k]) {
            float s = g_nms_sc[b * FLATN + i];
            unsigned u = __float_as_uint(s);
            u = (u & 0x80000000u) ? ~u : (u | 0x80000000u);
            key[k] = ((unsigned long long)u << 16) | (unsigned)(65535 - i);
        }
    }
    if (t == 0) { s_target = MAXDET; s_prefix = 0ull; }
    __syncthreads();

    unsigned long long prefix = 0ull;
    for (int lvl = 0; lvl < 6; lvl++) {
        int shift = 40 - 8 * lvl;
        if (t < 256) s_hist[t] = 0;
        __syncthreads();
        unsigned long long himask = (lvl == 0) ? 0ull : (~0ull << (shift + 8));
#pragma unroll
        for (int k = 0; k < 6; k++) {
            bool f = kv[k] && ((key[k] & himask) == prefix);
            int bin = (int)((key[k] >> shift) & 255);
            hist_add(s_hist, f ? bin : 0, f);
        }
        __syncthreads();
        int h = 0, x = 0;
        if (t < 256) {
            int bin = 255 - t;
            h = s_hist[bin];
            x = h;
#pragma unroll
            for (int off = 1; off < 32; off <<= 1) {
                int y = __shfl_up_sync(0xffffffffu, x, off);
                if ((t & 31) >= off) x += y;
            }
            if ((t & 31) == 31) s_wsum[t >> 5] = x;
        }
        __syncthreads();
        if (t < 256) {
            int add = 0, wid = t >> 5;
            for (int w = 0; w < wid; w++) add += s_wsum[w];
            int incl = x + add, excl = incl - h;
            int target = s_target;
            if (excl < target && target <= incl) {
                s_newbin = 255 - t;
                s_newtarget = target - excl;
            }
        }
        __syncthreads();
        if (t == 0) {
            s_target = s_newtarget;
            s_prefix = prefix | ((unsigned long long)s_newbin << shift);
        }
        __syncthreads();
        prefix = s_prefix;
    }

    if (t == 0) s_cnt = 0;
    __syncthreads();
#pragma unroll
    for (int k = 0; k < 6; k++) {
        bool f = kv[k] && (key[k] >= prefix);
        int pos = warp_agg_inc(&s_cnt, f);
        if (f && pos < 512) ck[pos] = key[k];
    }
    __syncthreads();
    for (int i = s_cnt + t; i < 512; i += NTHR) ck[i] = 0ull;
    __syncthreads();

    for (int k2 = 2; k2 <= 512; k2 <<= 1) {
        for (int j = k2 >> 1; j > 0; j >>= 1) {
            if (t < 512) {
                int i = t, l = i ^ j;
                if (l > i) {
                    unsigned long long a = ck[i];
                    unsigned long long bk = ck[l];
                    bool up = ((i & k2) == 0);
                    bool sw = up ? (a < bk) : (a > bk);
                    if (sw) { ck[i] = bk; ck[l] = a; }
                }
            }
            int nj = (j > 1) ? (j >> 1) : k2;
            if (j >= 32 || nj >= 32) __syncthreads();
            else __syncwarp();
        }
    }
    __syncthreads();

    if (t < MAXDET) {
        unsigned long long kk = ck[t];
        unsigned u = (unsigned)(kk >> 16);
        float s = (u & 0x80000000u) ? __uint_as_float(u ^ 0x80000000u)
                                    : __uint_as_float(~u);
        bool valid = s > NEG_HALF;
        float b0 = -1.0f, b1 = -1.0f, b2 = -1.0f, b3 = -1.0f;
        float scv = -1.0f, lab = -1.0f;
        if (valid) {
            int flat = 65535 - (int)(kk & 0xFFFFull);
            int c = flat / MAXDET;
            int bi = g_nms_idx[b * FLATN + flat];
            float4 bb = g_boxes[b * NN + bi];
            b0 = bb.x; b1 = bb.y; b2 = bb.z; b3 = bb.w;
            scv = s;
            lab = (float)c;
        }
        out[b * (MAXDET * 4) + t * 4 + 0] = b0;
        out[b * (MAXDET * 4) + t * 4 + 1] = b1;
        out[b * (MAXDET * 4) + t * 4 + 2] = b2;
        out[b * (MAXDET * 4) + t * 4 + 3] = b3;
        out[BB * MAXDET * 4 + b * MAXDET + t] = scv;
        out[BB * MAXDET * 4 + BB * MAXDET + b * MAXDET + t] = lab;
    }
}

// ---------------- launch ----------------
extern "C" void kernel_launch(void* const* d_in, const int* in_sizes, int n_in,
                              void* d_out, int out_size) {
    const float* anchors = (const float*)d_in[1];
    const float* deltas  = (const float*)d_in[2];
    const float* cls     = (const float*)d_in[3];
    float* out = (float*)d_out;

    cudaFuncSetAttribute(nms_pair_kernel, cudaFuncAttributeMaxDynamicSharedMemorySize,
                         64 * 1024);

    prep_kernel<<<(BB * NN + 255) / 256, 256>>>(anchors, deltas);
    nms_pair_kernel<<<BB * CC, NTHR, CAND_CAP * (int)sizeof(unsigned long long)>>>(cls);
    merge_kernel<<<BB, NTHR>>>(out);
}

// round 16
// speedup vs baseline: 1.3485x; 1.3485x over previous
#include <cuda_runtime.h>

#define BB 2
#define NN 49104
#define CC 20
#define NPAD 49152
#define MAXDET 300
#define NEGV (-1e9f)
#define NEG_HALF (-5e8f)
#define NTHR 1024
#define ELEMS (NPAD / NTHR)   // 48
#define FLATN (CC * MAXDET)   // 6000
#define TARGETC 1792
#define CAND_CAP 4096
#define WBUF 256              // per-warp stack slots
#define GSZ 256
#define GW (GSZ / 32)         // 8 mask words
#define LADDERN 8

__constant__ float c_ladder[LADDERN] =
    {0.58167f, 0.570f, 0.545f, 0.515f, 0.485f, 0.455f, 0.425f, 0.395f};

// ---------------- device scratch ----------------
__device__ float4 g_boxes[BB * NN];
__device__ float  g_nms_sc[BB * FLATN];
__device__ int    g_nms_idx[BB * FLATN];

// ---------------- warp helpers ----------------
__device__ __forceinline__ void hist_add(int* hist, int bin, bool flag) {
    unsigned act = __ballot_sync(0xffffffffu, flag);
    if (flag) {
        unsigned peers = __match_any_sync(act, bin);
        int leader = __ffs(peers) - 1;
        if ((int)(threadIdx.x & 31) == leader) atomicAdd(&hist[bin], __popc(peers));
    }
}

__device__ __forceinline__ int warp_agg_inc(int* ctr, bool flag) {
    unsigned act = __ballot_sync(0xffffffffu, flag);
    if (flag) {
        int lane = threadIdx.x & 31;
        int leader = __ffs(act) - 1;
        int base = 0;
        if (lane == leader) base = atomicAdd(ctr, __popc(act));
        base = __shfl_sync(act, base, leader);
        return base + __popc(act & ((1u << lane) - 1u));
    }
    return -1;
}

// ---------------- decode + clip (exact) ----------------
__global__ void prep_kernel(const float* __restrict__ anchors,
                            const float* __restrict__ deltas) {
    int i = blockIdx.x * blockDim.x + threadIdx.x;
    if (i >= BB * NN) return;
    float4 a = ((const float4*)anchors)[i];
    float4 d = ((const float4*)deltas)[i];
    float w = __fsub_rn(a.z, a.x);
    float h = __fsub_rn(a.w, a.y);
    float x1 = __fadd_rn(a.x, __fmul_rn(__fmul_rn(d.x, 0.2f), w));
    float y1 = __fadd_rn(a.y, __fmul_rn(__fmul_rn(d.y, 0.2f), h));
    float x2 = __fadd_rn(a.z, __fmul_rn(__fmul_rn(d.z, 0.2f), w));
    float y2 = __fadd_rn(a.w, __fmul_rn(__fmul_rn(d.w, 0.2f), h));
    x1 = fminf(fmaxf(x1, 0.0f), 511.0f);
    y1 = fminf(fmaxf(y1, 0.0f), 511.0f);
    x2 = fminf(fmaxf(x2, 0.0f), 511.0f);
    y2 = fminf(fmaxf(y2, 0.0f), 511.0f);
    g_boxes[i] = make_float4(x1, y1, x2, y2);
}

// exact IoU > 0.5, precomputed areas, early exit (bit-identical: inter==0 -> iou==0)
__device__ __forceinline__ bool iou_gt_half_pa(float4 a, float aa, float4 b, float ab) {
    float xx1 = fmaxf(a.x, b.x);
    float yy1 = fmaxf(a.y, b.y);
    float xx2 = fminf(a.z, b.z);
    float yy2 = fminf(a.w, b.w);
    float iw = __fsub_rn(xx2, xx1);
    float ih = __fsub_rn(yy2, yy1);
    if (iw <= 0.0f || ih <= 0.0f) return false;
    float inter = __fmul_rn(iw, ih);
    float den = __fadd_rn(__fsub_rn(__fadd_rn(aa, ab), inter), 1e-8f);
    return __fdiv_rn(inter, den) > 0.5f;
}

__device__ __forceinline__ float box_area(float4 b) {
    return __fmul_rn(__fsub_rn(b.z, b.x), __fsub_rn(b.w, b.y));
}

// ---------------- per (batch, class) sorted-order greedy NMS ----------------
__global__ __launch_bounds__(NTHR, 1) void nms_pair_kernel(const float* __restrict__ cls) {
    extern __shared__ unsigned long long cand[];   // CAND_CAP + 32*WBUF u64
    __shared__ int      s_hist[256];
    __shared__ int      s_total;
    __shared__ int      s_target;
    __shared__ unsigned s_prefix;
    __shared__ int      s_cnt;
    __shared__ int      s_ovf;
    __shared__ int      s_wcnt[32];
    __shared__ int      s_woff[32];
    __shared__ unsigned long long s_bound;
    __shared__ float4   s_acc[MAXDET];
    __shared__ float    s_accA[MAXDET];
    __shared__ int      s_accN;
    __shared__ float4   s_gbox[GSZ];
    __shared__ uint4    s_mask4[GSZ * 2];          // row p: 8 words (alive-indexed)
    __shared__ unsigned s_dead[GW];
    __shared__ int      s_alive[GSZ];
    __shared__ float    s_aliveA[GSZ];
    __shared__ int      s_acmp[8];
    __shared__ int      s_aoff[8];
    __shared__ int      s_aliveN;

    unsigned* s_mask = (unsigned*)s_mask4;
    int pair = blockIdx.x;
    int b = pair / CC;
    int c = pair % CC;
    int t = threadIdx.x;
    int wid = t >> 5, lane = t & 31;
    const float* __restrict__ sp = cls + (size_t)b * NN * CC + c;   // score(n) = sp[n*CC]
    const float4* __restrict__ bx = g_boxes + b * NN;
    unsigned long long* wbuf = cand + CAND_CAP + (size_t)wid * WBUF;

    if (t < MAXDET) {
        g_nms_sc[pair * MAXDET + t] = NEGV;
        g_nms_idx[pair * MAXDET + t] = 0;
    }
    if (t == 0) { s_accN = 0; s_bound = ~0ull; }

    for (int round = 0; ; round++) {
        __syncthreads();
        if (s_accN >= MAXDET) break;
        unsigned long long bound = s_bound;
        bool radix = (round >= LADDERN);
        float tau = radix ? 0.0f : c_ladder[round];
        int m = 0;

        if (!radix) {
            // ---- zero-atomic warp-stack compaction of window (tau, bound] ----
            int wcnt = 0;
#pragma unroll 4
            for (int k = 0; k < ELEMS; k++) {
                int n = t + k * NTHR;
                float v = (n < NN) ? __ldg(sp + (size_t)n * CC) : -1.0f;
                bool f = false;
                unsigned long long key = 0;
                if (v > tau) {
                    unsigned u = __float_as_uint(v);
                    key = ((unsigned long long)u << 32) | (unsigned)(0xFFFFFFFFu - (unsigned)n);
                    f = (key < bound);
                }
                unsigned ball = __ballot_sync(0xffffffffu, f);
                if (f) {
                    int off = wcnt + __popc(ball & ((1u << lane) - 1u));
                    if (off < WBUF) wbuf[off] = key;
                }
                wcnt += __popc(ball);
            }
            if (lane == 0) s_wcnt[wid] = wcnt;
            __syncthreads();
            if (t < 32) {
                int cv = s_wcnt[t];
                unsigned ovb = __ballot_sync(0xffffffffu, cv > WBUF);
                int x = cv;
#pragma unroll
                for (int off = 1; off < 32; off <<= 1) {
                    int y = __shfl_up_sync(0xffffffffu, x, off);
                    if (t >= off) x += y;
                }
                s_woff[t] = x - cv;
                if (t == 31) { s_cnt = x; s_ovf = (ovb != 0) ? 1 : 0; }
            }
            __syncthreads();
            m = s_cnt;
            if (s_ovf || m > CAND_CAP) {
                radix = true;                      // adversarial overflow -> exact radix
            } else if (m == 0) {
                if (t == 0)
                    s_bound = ((unsigned long long)(__float_as_uint(tau) + 1)) << 32;
                continue;
            } else {
                int off = s_woff[wid], cw = s_wcnt[wid];
                for (int i = lane; i < cw; i += 32) cand[off + i] = wbuf[i];
            }
        }

        if (radix) {
            // ---- exact 4-level byte-radix select among remaining (rare path) ----
            if (t == 0) { s_prefix = 0u; s_total = 0; s_target = 0; }
            __syncthreads();
            unsigned prefix = 0u;
            for (int lvl = 0; lvl < 4; lvl++) {
                int shift = 24 - lvl * 8;
                if (t < 256) s_hist[t] = 0;
                __syncthreads();
                unsigned himask = (lvl == 0) ? 0u : (0xFFFFFFFFu << (shift + 8));
                for (int k = 0; k < ELEMS; k++) {
                    int n = t + k * NTHR;
                    float v = (n < NN) ? __ldg(sp + (size_t)n * CC) : -1.0f;
                    bool f = false;
                    int bin = 0;
                    if (v > 0.05f) {
                        unsigned u = __float_as_uint(v);
                        if ((u & himask) == (prefix & himask)) {
                            unsigned long long key =
                                ((unsigned long long)u << 32) | (unsigned)(0xFFFFFFFFu - (unsigned)n);
                            if (key < bound) { f = true; bin = (u >> shift) & 255; }
                        }
                    }
                    hist_add(s_hist, bin, f);
                }
                __syncthreads();
                if (t == 0) {
                    if (lvl == 0) {
                        int tot = 0;
                        for (int i = 0; i < 256; i++) tot += s_hist[i];
                        s_total = tot;
                        s_target = tot < TARGETC ? tot : TARGETC;
                    }
                    if (s_total > 0) {
                        int cum = 0, bin = 0;
                        for (int i = 255; i >= 0; i--) {
                            int h = s_hist[i];
                            if (cum + h >= s_target) { bin = i; break; }
                            cum += h;
                        }
                        s_target -= cum;
                        s_prefix |= (unsigned)bin << shift;
                    }
                }
                __syncthreads();
                prefix = s_prefix;
                if (s_total == 0) break;
            }
            if (s_total == 0) break;   // pool exhausted -> remaining slots stay NEG
            unsigned s_star = prefix;

            if (t == 0) s_cnt = 0;
            __syncthreads();
            for (int k = 0; k < ELEMS; k++) {
                int n = t + k * NTHR;
                float v = (n < NN) ? __ldg(sp + (size_t)n * CC) : -1.0f;
                bool f = false;
                unsigned long long key = 0;
                if (v > 0.05f) {
                    unsigned u = __float_as_uint(v);
                    if (u >= s_star) {
                        key = ((unsigned long long)u << 32) | (unsigned)(0xFFFFFFFFu - (unsigned)n);
                        if (key < bound) f = true;
                    }
                }
                int pos = warp_agg_inc(&s_cnt, f);
                if (f && pos < CAND_CAP) cand[pos] = key;
            }
            __syncthreads();
            m = s_cnt < CAND_CAP ? s_cnt : CAND_CAP;
        }

        // ---- pad + bitonic sort descending (warp-sync small substeps) ----
        int sortn = 512;
        while (sortn < m) sortn <<= 1;
        for (int i = m + t; i < sortn; i += NTHR) cand[i] = 0ull;
        __syncthreads();
        for (int k2 = 2; k2 <= sortn; k2 <<= 1) {
            for (int j = k2 >> 1; j > 0; j >>= 1) {
                for (int i = t; i < sortn; i += NTHR) {
                    int l = i ^ j;
                    if (l > i) {
                        unsigned long long a = cand[i];
                        unsigned long long bb = cand[l];
                        bool up = ((i & k2) == 0);
                        bool sw = up ? (a < bb) : (a > bb);
                        if (sw) { cand[i] = bb; cand[l] = a; }
                    }
                }
                int nj = (j > 1) ? (j >> 1) : k2;
                if (j >= 32 || nj >= 32) __syncthreads();
                else __syncwarp();
            }
        }
        if (t == 0)
            s_bound = radix ? cand[m - 1]
                            : (((unsigned long long)(__float_as_uint(tau) + 1)) << 32);
        __syncthreads();

        // ---- walk sorted candidates in groups of GSZ ----
        for (int g0 = 0; g0 < m && s_accN < MAXDET; g0 += GSZ) {
            int gsz = min(GSZ, m - g0);
            for (int i = t; i < GSZ * 2; i += NTHR) s_mask4[i] = make_uint4(0, 0, 0, 0);
            if (t < GW) s_dead[t] = 0u;
            if (t < gsz) {
                unsigned long long key = cand[g0 + t];
                unsigned n = 0xFFFFFFFFu - (unsigned)(key & 0xFFFFFFFFull);
                s_gbox[t] = __ldg(&bx[n]);
            }
            __syncthreads();

            // stage 1: dead-check vs all accepted (4 segments per candidate)
            {
                int j = t & (GSZ - 1);
                int seg = t >> 8;
                if (j < gsz) {
                    float4 cb = s_gbox[j];
                    float ab_ = box_area(cb);
                    bool dead = false;
                    int accN = s_accN;
                    for (int i = seg; i < accN; i += 4)
                        if (iou_gt_half_pa(s_acc[i], s_accA[i], cb, ab_)) { dead = true; break; }
                    if (dead) atomicOr(&s_dead[j >> 5], 1u << (j & 31));
                }
            }
            __syncthreads();

            // stage 2: compact alive candidates (order-preserving)
            bool alv = (t < 256) && (t < gsz) && !((s_dead[t >> 5] >> (t & 31)) & 1u);
            unsigned ball = __ballot_sync(0xffffffffu, alv);
            if (t < 256 && lane == 0) s_acmp[wid] = __popc(ball);
            __syncthreads();
            if (t == 0) {
                int acc0 = 0;
#pragma unroll
                for (int w = 0; w < 8; w++) { s_aoff[w] = acc0; acc0 += s_acmp[w]; }
                s_aliveN = acc0;
            }
            __syncthreads();
            if (alv) {
                int pos = s_aoff[wid] + __popc(ball & ((1u << lane) - 1u));
                s_alive[pos] = t;
                s_aliveA[pos] = box_area(s_gbox[t]);
            }
            __syncthreads();
            int a = s_aliveN;
            if (a == 0) continue;

            // stage 3: pairwise among alive only (row per warp, lanes over cols)
            for (int ii = wid; ii < a; ii += 32) {
                float4 bi = s_gbox[s_alive[ii]];
                float ai = s_aliveA[ii];
                for (int jj = ii + 1 + lane; jj < a; jj += 32) {
                    if (iou_gt_half_pa(bi, ai, s_gbox[s_alive[jj]], s_aliveA[jj]))
                        atomicOr(&s_mask[ii * GW + (jj >> 5)], 1u << (jj & 31));
                }
            }
            __syncthreads();

            // stage 4: serial in-order resolution by t0 (register alive mask over a)
            if (t == 0) {
                unsigned aw[GW];
#pragma unroll
                for (int w = 0; w < GW; w++) {
                    int rem = a - w * 32;
                    aw[w] = (rem >= 32) ? 0xFFFFFFFFu
                          : (rem <= 0 ? 0u : ((1u << rem) - 1u));
                }
                int acc = s_accN;
                while (acc < MAXDET) {
                    int p = -1;
#pragma unroll
                    for (int w = GW - 1; w >= 0; w--)
                        if (aw[w]) p = w * 32 + __ffs(aw[w]) - 1;
                    if (p < 0) break;
                    uint4 m0 = s_mask4[p * 2];
                    uint4 m1 = s_mask4[p * 2 + 1];
                    aw[p >> 5] &= ~(1u << (p & 31));
                    aw[0] &= ~m0.x; aw[1] &= ~m0.y; aw[2] &= ~m0.z; aw[3] &= ~m0.w;
                    aw[4] &= ~m1.x; aw[5] &= ~m1.y; aw[6] &= ~m1.z; aw[7] &= ~m1.w;
                    int cj = s_alive[p];
                    unsigned long long key = cand[g0 + cj];
                    unsigned n = 0xFFFFFFFFu - (unsigned)(key & 0xFFFFFFFFull);
                    g_nms_sc[pair * MAXDET + acc] = __uint_as_float((unsigned)(key >> 32));
                    g_nms_idx[pair * MAXDET + acc] = (int)n;
                    s_acc[acc] = s_gbox[cj];
                    s_accA[acc] = s_aliveA[p];
                    acc++;
                }
                s_accN = acc;
            }
            __syncthreads();
        }
    }
}

// ------- merge: exact 6-level u64 radix select (parallel bin scan) + tiny sort -------
__global__ __launch_bounds__(NTHR, 1) void merge_kernel(float* __restrict__ out) {
    __shared__ int      s_hist[256];
    __shared__ int      s_wsum[8];
    __shared__ unsigned long long s_prefix;
    __shared__ int      s_target;
    __shared__ int      s_newbin;
    __shared__ int      s_newtarget;
    __shared__ int      s_cnt;
    __shared__ unsigned long long ck[512];
    int b = blockIdx.x;
    int t = threadIdx.x;

    unsigned long long key[6];
    bool kv[6];
#pragma unroll
    for (int k = 0; k < 6; k++) {
        int i = t + k * NTHR;
        kv[k] = (i < FLATN);
        key[k] = 0ull;
        if (kv[k]) {
            float s = g_nms_sc[b * FLATN + i];
            unsigned u = __float_as_uint(s);
            u = (u & 0x80000000u) ? ~u : (u | 0x80000000u);
            key[k] = ((unsigned long long)u << 16) | (unsigned)(65535 - i);
        }
    }
    if (t == 0) { s_target = MAXDET; s_prefix = 0ull; }
    __syncthreads();

    unsigned long long prefix = 0ull;
    for (int lvl = 0; lvl < 6; lvl++) {
        int shift = 40 - 8 * lvl;
        if (t < 256) s_hist[t] = 0;
        __syncthreads();
        unsigned long long himask = (lvl == 0) ? 0ull : (~0ull << (shift + 8));
#pragma unroll
        for (int k = 0; k < 6; k++) {
            bool f = kv[k] && ((key[k] & himask) == prefix);
            int bin = (int)((key[k] >> shift) & 255);
            hist_add(s_hist, f ? bin : 0, f);
        }
        __syncthreads();
        int h = 0, x = 0;
        if (t < 256) {
            int bin = 255 - t;
            h = s_hist[bin];
            x = h;
#pragma unroll
            for (int off = 1; off < 32; off <<= 1) {
                int y = __shfl_up_sync(0xffffffffu, x, off);
                if ((t & 31) >= off) x += y;
            }
            if ((t & 31) == 31) s_wsum[t >> 5] = x;
        }
        __syncthreads();
        if (t < 256) {
            int add = 0, wid = t >> 5;
            for (int w = 0; w < wid; w++) add += s_wsum[w];
            int incl = x + add, excl = incl - h;
            int target = s_target;
            if (excl < target && target <= incl) {
                s_newbin = 255 - t;
                s_newtarget = target - excl;
            }
        }
        __syncthreads();
        if (t == 0) {
            s_target = s_newtarget;
            s_prefix = prefix | ((unsigned long long)s_newbin << shift);
        }
        __syncthreads();
        prefix = s_prefix;
    }

    if (t == 0) s_cnt = 0;
    __syncthreads();
#pragma unroll
    for (int k = 0; k < 6; k++) {
        bool f = kv[k] && (key[k] >= prefix);
        int pos = warp_agg_inc(&s_cnt, f);
        if (f && pos < 512) ck[pos] = key[k];
    }
    __syncthreads();
    for (int i = s_cnt + t; i < 512; i += NTHR) ck[i] = 0ull;
    __syncthreads();

    for (int k2 = 2; k2 <= 512; k2 <<= 1) {
        for (int j = k2 >> 1; j > 0; j >>= 1) {
            if (t < 512) {
                int i = t, l = i ^ j;
                if (l > i) {
                    unsigned long long a = ck[i];
                    unsigned long long bk = ck[l];
                    bool up = ((i & k2) == 0);
                    bool sw = up ? (a < bk) : (a > bk);
                    if (sw) { ck[i] = bk; ck[l] = a; }
                }
            }
            int nj = (j > 1) ? (j >> 1) : k2;
            if (j >= 32 || nj >= 32) __syncthreads();
            else __syncwarp();
        }
    }
    __syncthreads();

    if (t < MAXDET) {
        unsigned long long kk = ck[t];
        unsigned u = (unsigned)(kk >> 16);
        float s = (u & 0x80000000u) ? __uint_as_float(u ^ 0x80000000u)
                                    : __uint_as_float(~u);
        bool valid = s > NEG_HALF;
        float b0 = -1.0f, b1 = -1.0f, b2 = -1.0f, b3 = -1.0f;
        float scv = -1.0f, lab = -1.0f;
        if (valid) {
            int flat = 65535 - (int)(kk & 0xFFFFull);
            int c = flat / MAXDET;
            int bi = g_nms_idx[b * FLATN + flat];
            float4 bb = g_boxes[b * NN + bi];
            b0 = bb.x; b1 = bb.y; b2 = bb.z; b3 = bb.w;
            scv = s;
            lab = (float)c;
        }
        out[b * (MAXDET * 4) + t * 4 + 0] = b0;
        out[b * (MAXDET * 4) + t * 4 + 1] = b1;
        out[b * (MAXDET * 4) + t * 4 + 2] = b2;
        out[b * (MAXDET * 4) + t * 4 + 3] = b3;
        out[BB * MAXDET * 4 + b * MAXDET + t] = scv;
        out[BB * MAXDET * 4 + BB * MAXDET + b * MAXDET + t] = lab;
    }
}

// ---------------- launch ----------------
extern "C" void kernel_launch(void* const* d_in, const int* in_sizes, int n_in,
                              void* d_out, int out_size) {
    const float* anchors = (const float*)d_in[1];
    const float* deltas  = (const float*)d_in[2];
    const float* cls     = (const float*)d_in[3];
    float* out = (float*)d_out;

    int dynBytes = (CAND_CAP + 32 * WBUF) * (int)sizeof(unsigned long long);  // 96KB
    cudaFuncSetAttribute(nms_pair_kernel, cudaFuncAttributeMaxDynamicSharedMemorySize,
                         dynBytes);

    prep_kernel<<<(BB * NN + 255) / 256, 256>>>(anchors, deltas);
    nms_pair_kernel<<<BB * CC, NTHR, dynBytes>>>(cls);
    merge_kernel<<<BB, NTHR>>>(out);
}